// round 1
// baseline (speedup 1.0000x reference)
#include <cuda_runtime.h>
#include <cuda_bf16.h>

// MultiIndexSelect: out[to_i[j]] = mat_i[from_i[j]], i in {0,1,2}, j in [0,L)
// D = 64 floats per row = 16 float4 = 256 bytes.
// One row is handled by 16 consecutive threads, each moving one float4.
// Both src row and dst row are contiguous 256B segments -> fully coalesced.

#define ROW_F4 16  // 64 floats / 4

__global__ void __launch_bounds__(256) multi_index_select_kernel(
    const float4* __restrict__ m0,
    const float4* __restrict__ m1,
    const float4* __restrict__ m2,
    const int* __restrict__ f0,
    const int* __restrict__ f1,
    const int* __restrict__ f2,
    const int* __restrict__ t0,
    const int* __restrict__ t1,
    const int* __restrict__ t2,
    float4* __restrict__ out,
    int L)
{
    int gid  = blockIdx.x * blockDim.x + threadIdx.x;
    int row  = gid >> 4;        // which logical row (0 .. 3L-1)
    int lane = gid & (ROW_F4 - 1);

    if (row >= 3 * L) return;

    const float4* src;
    int fi, ti;
    if (row < L) {
        fi = __ldg(&f0[row]);
        ti = __ldg(&t0[row]);
        src = m0;
    } else if (row < 2 * L) {
        int r = row - L;
        fi = __ldg(&f1[r]);
        ti = __ldg(&t1[r]);
        src = m1;
    } else {
        int r = row - 2 * L;
        fi = __ldg(&f2[r]);
        ti = __ldg(&t2[r]);
        src = m2;
    }

    // 256B contiguous segment per row on both sides.
    out[(size_t)ti * ROW_F4 + lane] = __ldg(&src[(size_t)fi * ROW_F4 + lane]);
}

extern "C" void kernel_launch(void* const* d_in, const int* in_sizes, int n_in,
                              void* d_out, int out_size)
{
    const float4* m0 = (const float4*)d_in[0];
    const float4* m1 = (const float4*)d_in[1];
    const float4* m2 = (const float4*)d_in[2];
    const int*    f0 = (const int*)d_in[3];
    const int*    f1 = (const int*)d_in[4];
    const int*    f2 = (const int*)d_in[5];
    const int*    t0 = (const int*)d_in[6];
    const int*    t1 = (const int*)d_in[7];
    const int*    t2 = (const int*)d_in[8];
    float4* out = (float4*)d_out;

    int L = in_sizes[3];              // length of from0
    long long total_threads = (long long)3 * L * ROW_F4;
    int block = 256;
    int grid  = (int)((total_threads + block - 1) / block);

    multi_index_select_kernel<<<grid, block>>>(
        m0, m1, m2, f0, f1, f2, t0, t1, t2, out, L);
}

// round 2
// speedup vs baseline: 1.3689x; 1.3689x over previous
#include <cuda_runtime.h>
#include <cuda_bf16.h>

// MultiIndexSelect: out[to_i[j]] = mat_i[from_i[j]], i in {0,1,2}, j in [0,L)
// 64 floats/row = 16 float4 = 256 B. 16 lanes per row, one float4 per lane.
// Each thread processes 4 rows with front-batched gathers (MLP=4) to cover
// DRAM latency; both gather and scatter touch full contiguous 256B segments.

#define ROW_F4 16
#define RPT 4   // rows per thread

__global__ void __launch_bounds__(256) multi_index_select_kernel(
    const float4* __restrict__ m0,
    const float4* __restrict__ m1,
    const float4* __restrict__ m2,
    const int* __restrict__ f0,
    const int* __restrict__ f1,
    const int* __restrict__ f2,
    const int* __restrict__ t0,
    const int* __restrict__ t1,
    const int* __restrict__ t2,
    float4* __restrict__ out,
    int L)
{
    const int tid  = blockIdx.x * blockDim.x + threadIdx.x;
    const int lane = tid & (ROW_F4 - 1);
    const long long row0 = (long long)(tid >> 4) * RPT;
    const long long R = (long long)3 * L;

    const float4* src[RPT];
    int fi[RPT], ti[RPT];
    bool valid[RPT];

    // Phase 1: fetch all indices (L1-broadcast across the 16 lanes of a row)
    #pragma unroll
    for (int k = 0; k < RPT; k++) {
        long long row = row0 + k;
        valid[k] = (row < R);
        if (valid[k]) {
            if (row < L) {
                fi[k] = __ldg(&f0[row]);
                ti[k] = __ldg(&t0[row]);
                src[k] = m0;
            } else if (row < 2LL * L) {
                int r = (int)(row - L);
                fi[k] = __ldg(&f1[r]);
                ti[k] = __ldg(&t1[r]);
                src[k] = m1;
            } else {
                int r = (int)(row - 2LL * L);
                fi[k] = __ldg(&f2[r]);
                ti[k] = __ldg(&t2[r]);
                src[k] = m2;
            }
        }
    }

    // Phase 2: front-batched gathers — 4 independent LDG.128 in flight
    float4 v[RPT];
    #pragma unroll
    for (int k = 0; k < RPT; k++) {
        if (valid[k])
            v[k] = __ldg(&src[k][(size_t)fi[k] * ROW_F4 + lane]);
    }

    // Phase 3: scatter stores (full 256B segments, write-combine friendly)
    #pragma unroll
    for (int k = 0; k < RPT; k++) {
        if (valid[k])
            out[(size_t)ti[k] * ROW_F4 + lane] = v[k];
    }
}

extern "C" void kernel_launch(void* const* d_in, const int* in_sizes, int n_in,
                              void* d_out, int out_size)
{
    const float4* m0 = (const float4*)d_in[0];
    const float4* m1 = (const float4*)d_in[1];
    const float4* m2 = (const float4*)d_in[2];
    const int*    f0 = (const int*)d_in[3];
    const int*    f1 = (const int*)d_in[4];
    const int*    f2 = (const int*)d_in[5];
    const int*    t0 = (const int*)d_in[6];
    const int*    t1 = (const int*)d_in[7];
    const int*    t2 = (const int*)d_in[8];
    float4* out = (float4*)d_out;

    int L = in_sizes[3];
    long long rows = (long long)3 * L;
    long long row_groups = (rows + RPT - 1) / RPT;
    long long total_threads = row_groups * ROW_F4;
    int block = 256;
    int grid  = (int)((total_threads + block - 1) / block);

    multi_index_select_kernel<<<grid, block>>>(
        m0, m1, m2, f0, f1, f2, t0, t1, t2, out, L);
}

// round 5
// speedup vs baseline: 1.3855x; 1.0121x over previous
#include <cuda_runtime.h>
#include <cuda_bf16.h>

// MultiIndexSelect: out[to_i[j]] = mat_i[from_i[j]], i in {0,1,2}, j in [0,L)
// 64 floats/row = 16 float4 = 256 B. 16 lanes per row, one float4 per lane.
// RPT=4 rows per thread, front-batched gathers (MLP=4).
// Fast path (L % 4 == 0): per-thread 4-row group lies in a single stream;
// indices loaded as one int4 each; streaming stores keep L2 for gather reuse.

#define ROW_F4 16
#define RPT 4

__global__ void __launch_bounds__(256) mis_fast_kernel(
    const float4* __restrict__ m0,
    const float4* __restrict__ m1,
    const float4* __restrict__ m2,
    const int* __restrict__ f0,
    const int* __restrict__ f1,
    const int* __restrict__ f2,
    const int* __restrict__ t0,
    const int* __restrict__ t1,
    const int* __restrict__ t2,
    float4* __restrict__ out,
    int L)
{
    const int tid   = blockIdx.x * blockDim.x + threadIdx.x;
    const int lane  = tid & (ROW_F4 - 1);
    const long long row0 = (long long)(tid >> 4) * RPT;
    const long long R = (long long)3 * L;
    if (row0 >= R) return;   // L%4==0 guarantees full groups

    // Resolve stream once per thread (group never crosses a boundary).
    const float4* src;
    const int* fp;
    const int* tp;
    int r0;
    if (row0 < L)            { src = m0; fp = f0; tp = t0; r0 = (int)row0; }
    else if (row0 < 2LL * L) { src = m1; fp = f1; tp = t1; r0 = (int)(row0 - L); }
    else                     { src = m2; fp = f2; tp = t2; r0 = (int)(row0 - 2LL * L); }

    // One vector load each for 4 consecutive from- and to-indices.
    const int4 fi = __ldg((const int4*)(fp + r0));
    const int4 ti = __ldg((const int4*)(tp + r0));

    // Front-batched gathers: 4 independent LDG.128 in flight.
    float4 v0 = __ldg(&src[(size_t)fi.x * ROW_F4 + lane]);
    float4 v1 = __ldg(&src[(size_t)fi.y * ROW_F4 + lane]);
    float4 v2 = __ldg(&src[(size_t)fi.z * ROW_F4 + lane]);
    float4 v3 = __ldg(&src[(size_t)fi.w * ROW_F4 + lane]);

    // Streaming scatter stores (evict-first: output is never re-read).
    __stcs(&out[(size_t)ti.x * ROW_F4 + lane], v0);
    __stcs(&out[(size_t)ti.y * ROW_F4 + lane], v1);
    __stcs(&out[(size_t)ti.z * ROW_F4 + lane], v2);
    __stcs(&out[(size_t)ti.w * ROW_F4 + lane], v3);
}

// Generic fallback (any L): per-row stream resolution + bounds checks.
__global__ void __launch_bounds__(256) mis_generic_kernel(
    const float4* __restrict__ m0,
    const float4* __restrict__ m1,
    const float4* __restrict__ m2,
    const int* __restrict__ f0,
    const int* __restrict__ f1,
    const int* __restrict__ f2,
    const int* __restrict__ t0,
    const int* __restrict__ t1,
    const int* __restrict__ t2,
    float4* __restrict__ out,
    int L)
{
    const int tid  = blockIdx.x * blockDim.x + threadIdx.x;
    const int lane = tid & (ROW_F4 - 1);
    const long long row0 = (long long)(tid >> 4) * RPT;
    const long long R = (long long)3 * L;

    const float4* src[RPT];
    int fi[RPT], ti[RPT];
    bool valid[RPT];

    #pragma unroll
    for (int k = 0; k < RPT; k++) {
        long long row = row0 + k;
        valid[k] = (row < R);
        if (valid[k]) {
            if (row < L)            { fi[k] = __ldg(&f0[row]);              ti[k] = __ldg(&t0[row]);              src[k] = m0; }
            else if (row < 2LL * L) { int r = (int)(row - L);      fi[k] = __ldg(&f1[r]); ti[k] = __ldg(&t1[r]); src[k] = m1; }
            else                    { int r = (int)(row - 2LL * L); fi[k] = __ldg(&f2[r]); ti[k] = __ldg(&t2[r]); src[k] = m2; }
        }
    }

    float4 v[RPT];
    #pragma unroll
    for (int k = 0; k < RPT; k++)
        if (valid[k]) v[k] = __ldg(&src[k][(size_t)fi[k] * ROW_F4 + lane]);

    #pragma unroll
    for (int k = 0; k < RPT; k++)
        if (valid[k]) __stcs(&out[(size_t)ti[k] * ROW_F4 + lane], v[k]);
}

extern "C" void kernel_launch(void* const* d_in, const int* in_sizes, int n_in,
                              void* d_out, int out_size)
{
    const float4* m0 = (const float4*)d_in[0];
    const float4* m1 = (const float4*)d_in[1];
    const float4* m2 = (const float4*)d_in[2];
    const int*    f0 = (const int*)d_in[3];
    const int*    f1 = (const int*)d_in[4];
    const int*    f2 = (const int*)d_in[5];
    const int*    t0 = (const int*)d_in[6];
    const int*    t1 = (const int*)d_in[7];
    const int*    t2 = (const int*)d_in[8];
    float4* out = (float4*)d_out;

    int L = in_sizes[3];
    long long rows = (long long)3 * L;
    long long row_groups = (rows + RPT - 1) / RPT;
    long long total_threads = row_groups * ROW_F4;
    int block = 256;
    int grid  = (int)((total_threads + block - 1) / block);

    if ((L % RPT) == 0) {
        mis_fast_kernel<<<grid, block>>>(
            m0, m1, m2, f0, f1, f2, t0, t1, t2, out, L);
    } else {
        mis_generic_kernel<<<grid, block>>>(
            m0, m1, m2, f0, f1, f2, t0, t1, t2, out, L);
    }
}